// round 1
// baseline (speedup 1.0000x reference)
#include <cuda_runtime.h>
#include <cuda_bf16.h>

#define N_NODES 10000
#define N_EDGES 640000
#define HID 128
#define N_GRAPHS 64

// ---------------- device scratch (no dynamic alloc allowed) ----------------
__device__ int   g_deg[N_NODES];
__device__ float g_dis[N_NODES];
__device__ int   g_rowptr[N_NODES + 1];
__device__ int   g_cursor[N_NODES];
__device__ int   g_col[N_EDGES];          // src ids grouped by dst (CSR)
__device__ int   g_cnt[N_GRAPHS];
__device__ float g_hs[N_NODES * HID];     // (X @ W) * dis[row]
__device__ float g_xb[N_NODES * HID];     // layer output / next layer input

// ---------------- init: zero deg, graph counts, and output ----------------
__global__ void init_kernel(float* out) {
    int i = blockIdx.x * blockDim.x + threadIdx.x;
    if (i < N_NODES) g_deg[i] = 0;
    if (i < N_GRAPHS) g_cnt[i] = 0;
    if (i < N_GRAPHS * HID) out[i] = 0.0f;
}

// ---------------- degree histogram over dst ----------------
__global__ void deg_kernel(const int* __restrict__ dst) {
    int e = blockIdx.x * blockDim.x + threadIdx.x;
    if (e < N_EDGES) atomicAdd(&g_deg[dst[e]], 1);
}

// ---------------- single-block scan: rowptr, cursor, dis ----------------
__global__ void scan_kernel() {
    __shared__ int ps[1024];
    const int C = 10;  // 1024 * 10 >= N_NODES
    int tid = threadIdx.x;
    int start = tid * C;
    int sum = 0;
#pragma unroll
    for (int i = 0; i < C; i++) {
        int idx = start + i;
        if (idx < N_NODES) sum += g_deg[idx];
    }
    ps[tid] = sum;
    __syncthreads();
    for (int off = 1; off < 1024; off <<= 1) {
        int v = (tid >= off) ? ps[tid - off] : 0;
        __syncthreads();
        ps[tid] += v;
        __syncthreads();
    }
    int run = (tid == 0) ? 0 : ps[tid - 1];
#pragma unroll
    for (int i = 0; i < C; i++) {
        int idx = start + i;
        if (idx < N_NODES) {
            int d = g_deg[idx];
            g_rowptr[idx] = run;
            g_cursor[idx] = run;
            g_dis[idx] = rsqrtf((float)(d + 1));
            run += d;
        }
    }
    if (tid == 1023) g_rowptr[N_NODES] = ps[1023];
}

// ---------------- CSR fill (+ batch counts piggybacked) ----------------
__global__ void fill_kernel(const int* __restrict__ src, const int* __restrict__ dst,
                            const int* __restrict__ batch) {
    int e = blockIdx.x * blockDim.x + threadIdx.x;
    if (e < N_EDGES) {
        int d = dst[e];
        int p = atomicAdd(&g_cursor[d], 1);
        g_col[p] = src[e];
    }
    if (e < N_NODES) atomicAdd(&g_cnt[batch[e]], 1);
}

// ---------------- SGEMM: H[r][c] = (sum_k X[r][k]*W[k][c]) * dis[r] ----------------
// BM=64, BN=128(full), BK=32, 256 threads, thread tile 4x8.
#define BM 64
#define BK 32
__global__ __launch_bounds__(256) void gemm_kernel(const float* __restrict__ X,
                                                   const float* __restrict__ W,
                                                   float* __restrict__ H, int M) {
    __shared__ float Xs[BM][BK + 1];
    __shared__ float Ws[BK][HID];
    int tid = threadIdx.x;
    int tx = tid & 15;        // 16 col groups of 8
    int ty = tid >> 4;        // 16 row groups of 4
    int rb = blockIdx.x * BM;

    float acc[4][8];
#pragma unroll
    for (int i = 0; i < 4; i++)
#pragma unroll
        for (int j = 0; j < 8; j++) acc[i][j] = 0.0f;

    for (int kt = 0; kt < HID; kt += BK) {
        // load X tile: 64x32 = 512 float4, 2 per thread
#pragma unroll
        for (int u = 0; u < 2; u++) {
            int id = tid * 2 + u;
            int row = id >> 3;
            int cf = (id & 7) * 4;
            float4 v = make_float4(0.f, 0.f, 0.f, 0.f);
            int gr = rb + row;
            if (gr < M) v = *(const float4*)&X[gr * HID + kt + cf];
            Xs[row][cf + 0] = v.x; Xs[row][cf + 1] = v.y;
            Xs[row][cf + 2] = v.z; Xs[row][cf + 3] = v.w;
        }
        // load W tile: 32x128 = 1024 float4, 4 per thread
#pragma unroll
        for (int u = 0; u < 4; u++) {
            int id = tid + u * 256;
            int row = id >> 5;
            int cf = (id & 31) * 4;
            *(float4*)&Ws[row][cf] = *(const float4*)&W[(kt + row) * HID + cf];
        }
        __syncthreads();
#pragma unroll
        for (int kk = 0; kk < BK; kk++) {
            float a[4], b[8];
#pragma unroll
            for (int i = 0; i < 4; i++) a[i] = Xs[ty * 4 + i][kk];
#pragma unroll
            for (int j = 0; j < 8; j++) b[j] = Ws[kk][tx * 8 + j];
#pragma unroll
            for (int i = 0; i < 4; i++)
#pragma unroll
                for (int j = 0; j < 8; j++) acc[i][j] = fmaf(a[i], b[j], acc[i][j]);
        }
        __syncthreads();
    }
#pragma unroll
    for (int i = 0; i < 4; i++) {
        int gr = rb + ty * 4 + i;
        if (gr < M) {
            float d = g_dis[gr];
            float4 v0, v1;
            v0.x = acc[i][0] * d; v0.y = acc[i][1] * d;
            v0.z = acc[i][2] * d; v0.w = acc[i][3] * d;
            v1.x = acc[i][4] * d; v1.y = acc[i][5] * d;
            v1.z = acc[i][6] * d; v1.w = acc[i][7] * d;
            *(float4*)&H[gr * HID + tx * 8 + 0] = v0;
            *(float4*)&H[gr * HID + tx * 8 + 4] = v1;
        }
    }
}

// ---------------- aggregation: warp per node, CSR gather ----------------
// out[i] = dis[i] * (hs[i] + sum_{e: dst=i} hs[src_e]) + b ; optional relu
__global__ __launch_bounds__(256) void agg_kernel(const float* __restrict__ HS,
                                                  const float* __restrict__ bias,
                                                  float* __restrict__ OUT, int relu) {
    int warp = (blockIdx.x * blockDim.x + threadIdx.x) >> 5;
    int lane = threadIdx.x & 31;
    if (warp >= N_NODES) return;
    int e0 = g_rowptr[warp];
    int e1 = g_rowptr[warp + 1];
    float4 acc = *(const float4*)&HS[warp * HID + lane * 4];  // self-loop term
    for (int base = e0; base < e1; base += 32) {
        int s = 0;
        if (base + lane < e1) s = g_col[base + lane];
        int n = min(32, e1 - base);
        for (int j = 0; j < n; j++) {
            int ss = __shfl_sync(0xffffffffu, s, j);
            float4 v = *(const float4*)&HS[ss * HID + lane * 4];
            acc.x += v.x; acc.y += v.y; acc.z += v.z; acc.w += v.w;
        }
    }
    float d = g_dis[warp];
    float4 bb = *(const float4*)&bias[lane * 4];
    float4 o;
    o.x = acc.x * d + bb.x;
    o.y = acc.y * d + bb.y;
    o.z = acc.z * d + bb.z;
    o.w = acc.w * d + bb.w;
    if (relu) {
        o.x = fmaxf(o.x, 0.f); o.y = fmaxf(o.y, 0.f);
        o.z = fmaxf(o.z, 0.f); o.w = fmaxf(o.w, 0.f);
    }
    *(float4*)&OUT[warp * HID + lane * 4] = o;
}

// ---------------- mean pool: atomic accumulate then divide ----------------
__global__ void pool_kernel(const float* __restrict__ H, const int* __restrict__ batch,
                            float* __restrict__ out) {
    int warp = (blockIdx.x * blockDim.x + threadIdx.x) >> 5;
    int lane = threadIdx.x & 31;
    if (warp >= N_NODES) return;
    int g = batch[warp];
    float4 v = *(const float4*)&H[warp * HID + lane * 4];
    atomicAdd(&out[g * HID + lane * 4 + 0], v.x);
    atomicAdd(&out[g * HID + lane * 4 + 1], v.y);
    atomicAdd(&out[g * HID + lane * 4 + 2], v.z);
    atomicAdd(&out[g * HID + lane * 4 + 3], v.w);
}

__global__ void div_kernel(float* __restrict__ out) {
    int i = blockIdx.x * blockDim.x + threadIdx.x;
    if (i < N_GRAPHS * HID) {
        int g = i >> 7;
        float c = (float)max(g_cnt[g], 1);
        out[i] = out[i] / c;
    }
}

// ---------------- launch ----------------
extern "C" void kernel_launch(void* const* d_in, const int* in_sizes, int n_in,
                              void* d_out, int out_size) {
    const float* x     = (const float*)d_in[0];
    const int*   eidx  = (const int*)d_in[1];
    const int*   batch = (const int*)d_in[2];
    const float* W0    = (const float*)d_in[3];
    const float* b0    = (const float*)d_in[4];
    const float* W1    = (const float*)d_in[5];
    const float* b1    = (const float*)d_in[6];
    const float* W2    = (const float*)d_in[7];
    const float* b2    = (const float*)d_in[8];
    float* out = (float*)d_out;

    const int* src = eidx;
    const int* dst = eidx + N_EDGES;

    float* hs = nullptr;
    float* xb = nullptr;
    cudaGetSymbolAddress((void**)&hs, g_hs);
    cudaGetSymbolAddress((void**)&xb, g_xb);

    init_kernel<<<(N_NODES + 255) / 256, 256>>>(out);
    deg_kernel<<<(N_EDGES + 255) / 256, 256>>>(dst);
    scan_kernel<<<1, 1024>>>();
    fill_kernel<<<(N_EDGES + 255) / 256, 256>>>(src, dst, batch);

    int gemm_grid = (N_NODES + BM - 1) / BM;
    int agg_grid = (N_NODES + 7) / 8;  // 8 warps per 256-thread block

    // layer 0
    gemm_kernel<<<gemm_grid, 256>>>(x, W0, hs, N_NODES);
    agg_kernel<<<agg_grid, 256>>>(hs, b0, xb, 1);
    // layer 1
    gemm_kernel<<<gemm_grid, 256>>>(xb, W1, hs, N_NODES);
    agg_kernel<<<agg_grid, 256>>>(hs, b1, xb, 1);
    // layer 2
    gemm_kernel<<<gemm_grid, 256>>>(xb, W2, hs, N_NODES);
    agg_kernel<<<agg_grid, 256>>>(hs, b2, xb, 0);

    pool_kernel<<<agg_grid, 256>>>(xb, batch, out);
    div_kernel<<<(N_GRAPHS * HID + 255) / 256, 256>>>(out);
}

// round 2
// speedup vs baseline: 1.1413x; 1.1413x over previous
#include <cuda_runtime.h>
#include <cuda_bf16.h>

#define N_NODES 10000
#define N_EDGES 640000
#define HID 128
#define N_GRAPHS 64

// ---------------- device scratch (no dynamic alloc allowed) ----------------
__device__ int   g_deg[N_NODES];
__device__ float g_dis[N_NODES];
__device__ int   g_rowptr[N_NODES + 1];
__device__ int   g_pos[N_EDGES];          // slot of edge within its dst row
__device__ int   g_col[N_EDGES];          // src ids grouped by dst (CSR)
__device__ float g_hs[N_NODES * HID];     // (X @ W) * dis[row]
__device__ float g_xb[N_NODES * HID];     // layer output / next layer input

// ---------------- degree histogram over dst; record slot per edge ----------
__global__ __launch_bounds__(256) void pos_kernel(const int* __restrict__ dst) {
    int base = (blockIdx.x * blockDim.x + threadIdx.x) * 4;
    if (base + 3 < N_EDGES) {
        int d0 = dst[base + 0];
        int d1 = dst[base + 1];
        int d2 = dst[base + 2];
        int d3 = dst[base + 3];
        g_pos[base + 0] = atomicAdd(&g_deg[d0], 1);
        g_pos[base + 1] = atomicAdd(&g_deg[d1], 1);
        g_pos[base + 2] = atomicAdd(&g_deg[d2], 1);
        g_pos[base + 3] = atomicAdd(&g_deg[d3], 1);
    } else {
        for (int e = base; e < N_EDGES; e++)
            g_pos[e] = atomicAdd(&g_deg[dst[e]], 1);
    }
}

// ---------------- single-block scan: rowptr, dis ----------------
__global__ void scan_kernel() {
    __shared__ int ps[1024];
    const int C = 10;  // 1024 * 10 >= N_NODES
    int tid = threadIdx.x;
    int start = tid * C;
    int sum = 0;
#pragma unroll
    for (int i = 0; i < C; i++) {
        int idx = start + i;
        if (idx < N_NODES) sum += g_deg[idx];
    }
    ps[tid] = sum;
    __syncthreads();
    for (int off = 1; off < 1024; off <<= 1) {
        int v = (tid >= off) ? ps[tid - off] : 0;
        __syncthreads();
        ps[tid] += v;
        __syncthreads();
    }
    int run = (tid == 0) ? 0 : ps[tid - 1];
#pragma unroll
    for (int i = 0; i < C; i++) {
        int idx = start + i;
        if (idx < N_NODES) {
            int d = g_deg[idx];
            g_rowptr[idx] = run;
            g_dis[idx] = rsqrtf((float)(d + 1));
            run += d;
        }
    }
    if (tid == 1023) g_rowptr[N_NODES] = ps[1023];
}

// ---------------- CSR fill: pure scatter, no atomics ----------------
__global__ __launch_bounds__(256) void fill_kernel(const int* __restrict__ src,
                                                   const int* __restrict__ dst) {
    int base = (blockIdx.x * blockDim.x + threadIdx.x) * 4;
    if (base + 3 < N_EDGES) {
        int d0 = dst[base + 0], d1 = dst[base + 1];
        int d2 = dst[base + 2], d3 = dst[base + 3];
        int p0 = g_rowptr[d0] + g_pos[base + 0];
        int p1 = g_rowptr[d1] + g_pos[base + 1];
        int p2 = g_rowptr[d2] + g_pos[base + 2];
        int p3 = g_rowptr[d3] + g_pos[base + 3];
        g_col[p0] = src[base + 0];
        g_col[p1] = src[base + 1];
        g_col[p2] = src[base + 2];
        g_col[p3] = src[base + 3];
    } else {
        for (int e = base; e < N_EDGES; e++)
            g_col[g_rowptr[dst[e]] + g_pos[e]] = src[e];
    }
}

// ---------------- SGEMM: H[r][c] = (sum_k X[r][k]*W[k][c]) * dis[r] ----------------
#define BM 64
#define BK 32
__global__ __launch_bounds__(256) void gemm_kernel(const float* __restrict__ X,
                                                   const float* __restrict__ W,
                                                   float* __restrict__ H, int M) {
    __shared__ float Xs[BM][BK + 1];
    __shared__ float Ws[BK][HID];
    int tid = threadIdx.x;
    int tx = tid & 15;        // 16 col groups of 8
    int ty = tid >> 4;        // 16 row groups of 4
    int rb = blockIdx.x * BM;

    float acc[4][8];
#pragma unroll
    for (int i = 0; i < 4; i++)
#pragma unroll
        for (int j = 0; j < 8; j++) acc[i][j] = 0.0f;

    for (int kt = 0; kt < HID; kt += BK) {
#pragma unroll
        for (int u = 0; u < 2; u++) {
            int id = tid * 2 + u;
            int row = id >> 3;
            int cf = (id & 7) * 4;
            float4 v = make_float4(0.f, 0.f, 0.f, 0.f);
            int gr = rb + row;
            if (gr < M) v = *(const float4*)&X[gr * HID + kt + cf];
            Xs[row][cf + 0] = v.x; Xs[row][cf + 1] = v.y;
            Xs[row][cf + 2] = v.z; Xs[row][cf + 3] = v.w;
        }
#pragma unroll
        for (int u = 0; u < 4; u++) {
            int id = tid + u * 256;
            int row = id >> 5;
            int cf = (id & 31) * 4;
            *(float4*)&Ws[row][cf] = *(const float4*)&W[(kt + row) * HID + cf];
        }
        __syncthreads();
#pragma unroll
        for (int kk = 0; kk < BK; kk++) {
            float a[4], b[8];
#pragma unroll
            for (int i = 0; i < 4; i++) a[i] = Xs[ty * 4 + i][kk];
#pragma unroll
            for (int j = 0; j < 8; j++) b[j] = Ws[kk][tx * 8 + j];
#pragma unroll
            for (int i = 0; i < 4; i++)
#pragma unroll
                for (int j = 0; j < 8; j++) acc[i][j] = fmaf(a[i], b[j], acc[i][j]);
        }
        __syncthreads();
    }
#pragma unroll
    for (int i = 0; i < 4; i++) {
        int gr = rb + ty * 4 + i;
        if (gr < M) {
            float d = g_dis[gr];
            float4 v0, v1;
            v0.x = acc[i][0] * d; v0.y = acc[i][1] * d;
            v0.z = acc[i][2] * d; v0.w = acc[i][3] * d;
            v1.x = acc[i][4] * d; v1.y = acc[i][5] * d;
            v1.z = acc[i][6] * d; v1.w = acc[i][7] * d;
            *(float4*)&H[gr * HID + tx * 8 + 0] = v0;
            *(float4*)&H[gr * HID + tx * 8 + 4] = v1;
        }
    }
}

// ---------------- aggregation: warp per node, CSR gather, unrolled ----------------
// out[i] = dis[i] * (hs[i] + sum_{e: dst=i} hs[src_e]) + b ; optional relu
__global__ __launch_bounds__(256) void agg_kernel(const float* __restrict__ HS,
                                                  const float* __restrict__ bias,
                                                  float* __restrict__ OUT, int relu) {
    int warp = (blockIdx.x * blockDim.x + threadIdx.x) >> 5;
    int lane = threadIdx.x & 31;
    if (warp >= N_NODES) return;
    int e0 = g_rowptr[warp];
    int e1 = g_rowptr[warp + 1];
    float4 acc = *(const float4*)&HS[warp * HID + lane * 4];  // self-loop term

    int base = e0;
    // full chunks of 32 edges: batch 8 independent loads at a time
    for (; base + 32 <= e1; base += 32) {
        int s = g_col[base + lane];
#pragma unroll
        for (int jj = 0; jj < 4; jj++) {
            float4 v[8];
#pragma unroll
            for (int j2 = 0; j2 < 8; j2++) {
                int ss = __shfl_sync(0xffffffffu, s, jj * 8 + j2);
                v[j2] = *(const float4*)&HS[ss * HID + lane * 4];
            }
#pragma unroll
            for (int j2 = 0; j2 < 8; j2++) {
                acc.x += v[j2].x; acc.y += v[j2].y;
                acc.z += v[j2].z; acc.w += v[j2].w;
            }
        }
    }
    // tail
    int rem = e1 - base;
    if (rem > 0) {
        int s = (lane < rem) ? g_col[base + lane] : 0;
        for (int j = 0; j < rem; j++) {
            int ss = __shfl_sync(0xffffffffu, s, j);
            float4 v = *(const float4*)&HS[ss * HID + lane * 4];
            acc.x += v.x; acc.y += v.y; acc.z += v.z; acc.w += v.w;
        }
    }

    float d = g_dis[warp];
    float4 bb = *(const float4*)&bias[lane * 4];
    float4 o;
    o.x = acc.x * d + bb.x;
    o.y = acc.y * d + bb.y;
    o.z = acc.z * d + bb.z;
    o.w = acc.w * d + bb.w;
    if (relu) {
        o.x = fmaxf(o.x, 0.f); o.y = fmaxf(o.y, 0.f);
        o.z = fmaxf(o.z, 0.f); o.w = fmaxf(o.w, 0.f);
    }
    *(float4*)&OUT[warp * HID + lane * 4] = o;
}

// ---------------- mean pool: batch is sorted -> segment sums, no atomics ----------
__device__ __forceinline__ int lower_bound_dev(const int* __restrict__ a, int n, int key) {
    int lo = 0, hi = n;
    while (lo < hi) {
        int mid = (lo + hi) >> 1;
        if (a[mid] < key) lo = mid + 1; else hi = mid;
    }
    return lo;
}

__global__ __launch_bounds__(256) void pool_kernel(const float* __restrict__ H,
                                                   const int* __restrict__ batch,
                                                   float* __restrict__ out) {
    int g = blockIdx.x;
    int t = threadIdx.x;          // 256 threads: 2 row-halves x 128 cols
    int lo = lower_bound_dev(batch, N_NODES, g);
    int hi = lower_bound_dev(batch, N_NODES, g + 1);
    int c = t & 127;
    int half = t >> 7;
    float sum = 0.0f;
    int r = lo + half;
    // unrolled by 4 (stride 2 rows per thread) for MLP
    for (; r + 6 < hi; r += 8) {
        float v0 = H[(r + 0) * HID + c];
        float v1 = H[(r + 2) * HID + c];
        float v2 = H[(r + 4) * HID + c];
        float v3 = H[(r + 6) * HID + c];
        sum += v0 + v1 + v2 + v3;
    }
    for (; r < hi; r += 2) sum += H[r * HID + c];
    __shared__ float red[256];
    red[t] = sum;
    __syncthreads();
    if (t < 128) {
        float tot = red[t] + red[t + 128];
        int n = hi - lo;
        out[g * HID + t] = tot / (float)max(n, 1);
    }
}

// ---------------- launch ----------------
extern "C" void kernel_launch(void* const* d_in, const int* in_sizes, int n_in,
                              void* d_out, int out_size) {
    const float* x     = (const float*)d_in[0];
    const int*   eidx  = (const int*)d_in[1];
    const int*   batch = (const int*)d_in[2];
    const float* W0    = (const float*)d_in[3];
    const float* b0    = (const float*)d_in[4];
    const float* W1    = (const float*)d_in[5];
    const float* b1    = (const float*)d_in[6];
    const float* W2    = (const float*)d_in[7];
    const float* b2    = (const float*)d_in[8];
    float* out = (float*)d_out;

    const int* src = eidx;
    const int* dst = eidx + N_EDGES;

    float* hs = nullptr;
    float* xb = nullptr;
    int* degp = nullptr;
    cudaGetSymbolAddress((void**)&hs, g_hs);
    cudaGetSymbolAddress((void**)&xb, g_xb);
    cudaGetSymbolAddress((void**)&degp, g_deg);

    cudaMemsetAsync(degp, 0, N_NODES * sizeof(int));

    int e4_grid = (N_EDGES / 4 + 255) / 256;
    pos_kernel<<<e4_grid, 256>>>(dst);
    scan_kernel<<<1, 1024>>>();
    fill_kernel<<<e4_grid, 256>>>(src, dst);

    int gemm_grid = (N_NODES + BM - 1) / BM;
    int agg_grid = (N_NODES + 7) / 8;  // 8 warps per 256-thread block

    // layer 0
    gemm_kernel<<<gemm_grid, 256>>>(x, W0, hs, N_NODES);
    agg_kernel<<<agg_grid, 256>>>(hs, b0, xb, 1);
    // layer 1
    gemm_kernel<<<gemm_grid, 256>>>(xb, W1, hs, N_NODES);
    agg_kernel<<<agg_grid, 256>>>(hs, b1, xb, 1);
    // layer 2
    gemm_kernel<<<gemm_grid, 256>>>(xb, W2, hs, N_NODES);
    agg_kernel<<<agg_grid, 256>>>(hs, b2, xb, 0);

    pool_kernel<<<N_GRAPHS, 256>>>(xb, batch, out);
}

// round 3
// speedup vs baseline: 1.3732x; 1.2032x over previous
#include <cuda_runtime.h>
#include <cuda_bf16.h>
#include <cstdint>

#define N_NODES 10000
#define N_EDGES 640000
#define HID 128
#define N_GRAPHS 64

// ---------------- device scratch (no dynamic alloc allowed) ----------------
__device__ int   g_deg[N_NODES];
__device__ float g_dis[N_NODES];
__device__ int   g_rowptr[N_NODES + 1];
__device__ int   g_pos[N_EDGES];          // slot of edge within its dst row
__device__ int   g_col[N_EDGES];          // src ids grouped by dst (CSR)
__device__ float g_hs[N_NODES * HID];     // (X @ W) * dis[row]
__device__ float g_xb[N_NODES * HID];     // layer output / next layer input

// ---------------- cp.async helpers ----------------
__device__ __forceinline__ void cp16(void* smem_dst, const void* gsrc) {
    uint32_t s = (uint32_t)__cvta_generic_to_shared(smem_dst);
    asm volatile("cp.async.cg.shared.global [%0], [%1], 16;" :: "r"(s), "l"(gsrc));
}
__device__ __forceinline__ void cp_commit() {
    asm volatile("cp.async.commit_group;" ::: "memory");
}
__device__ __forceinline__ void cp_wait0() {
    asm volatile("cp.async.wait_group 0;" ::: "memory");
}

// ---------------- degree histogram over dst; record slot per edge ----------
__global__ __launch_bounds__(256) void pos_kernel(const int* __restrict__ dst) {
    int base = (blockIdx.x * blockDim.x + threadIdx.x) * 4;
    if (base + 3 < N_EDGES) {
        int d0 = dst[base + 0];
        int d1 = dst[base + 1];
        int d2 = dst[base + 2];
        int d3 = dst[base + 3];
        g_pos[base + 0] = atomicAdd(&g_deg[d0], 1);
        g_pos[base + 1] = atomicAdd(&g_deg[d1], 1);
        g_pos[base + 2] = atomicAdd(&g_deg[d2], 1);
        g_pos[base + 3] = atomicAdd(&g_deg[d3], 1);
    } else {
        for (int e = base; e < N_EDGES; e++)
            g_pos[e] = atomicAdd(&g_deg[dst[e]], 1);
    }
}

// ---------------- single-block scan: rowptr, dis ----------------
__global__ void scan_kernel() {
    __shared__ int ps[1024];
    const int C = 10;  // 1024 * 10 >= N_NODES
    int tid = threadIdx.x;
    int start = tid * C;
    int sum = 0;
#pragma unroll
    for (int i = 0; i < C; i++) {
        int idx = start + i;
        if (idx < N_NODES) sum += g_deg[idx];
    }
    ps[tid] = sum;
    __syncthreads();
    for (int off = 1; off < 1024; off <<= 1) {
        int v = (tid >= off) ? ps[tid - off] : 0;
        __syncthreads();
        ps[tid] += v;
        __syncthreads();
    }
    int run = (tid == 0) ? 0 : ps[tid - 1];
#pragma unroll
    for (int i = 0; i < C; i++) {
        int idx = start + i;
        if (idx < N_NODES) {
            int d = g_deg[idx];
            g_rowptr[idx] = run;
            g_dis[idx] = rsqrtf((float)(d + 1));
            run += d;
        }
    }
    if (tid == 1023) g_rowptr[N_NODES] = ps[1023];
}

// ---------------- CSR fill: pure scatter, no atomics ----------------
__global__ __launch_bounds__(256) void fill_kernel(const int* __restrict__ src,
                                                   const int* __restrict__ dst) {
    int base = (blockIdx.x * blockDim.x + threadIdx.x) * 4;
    if (base + 3 < N_EDGES) {
        int d0 = dst[base + 0], d1 = dst[base + 1];
        int d2 = dst[base + 2], d3 = dst[base + 3];
        int p0 = g_rowptr[d0] + g_pos[base + 0];
        int p1 = g_rowptr[d1] + g_pos[base + 1];
        int p2 = g_rowptr[d2] + g_pos[base + 2];
        int p3 = g_rowptr[d3] + g_pos[base + 3];
        g_col[p0] = src[base + 0];
        g_col[p1] = src[base + 1];
        g_col[p2] = src[base + 2];
        g_col[p3] = src[base + 3];
    } else {
        for (int e = base; e < N_EDGES; e++)
            g_col[g_rowptr[dst[e]] + g_pos[e]] = src[e];
    }
}

// ---------------- SGEMM v3: H[r][c] = (sum_k X[r][k]*W[k][c]) * dis[r] ----------
// BM=32, BN=128(full), K=128 fully smem-resident X (transposed), W streamed
// in 4 chunks of 32 k-rows via cp.async double buffer. 256 threads, tile 4x4.
#define GBM 32
#define XS_STRIDE 33   // pad: STS conflicts 4-way, LDS of a is broadcast
// dynamic smem: Xs[128*33] floats + Ws[2*32*128] floats
#define GEMM_SMEM_BYTES ((128 * XS_STRIDE + 2 * 32 * HID) * 4)

__global__ __launch_bounds__(256) void gemm_kernel(const float* __restrict__ X,
                                                   const float* __restrict__ W,
                                                   float* __restrict__ H, int M) {
    extern __shared__ float sm[];
    float* Xs = sm;                       // [128][33], k-major (transposed)
    float* Ws = sm + 128 * XS_STRIDE;     // [2][32][128]
    int tid = threadIdx.x;
    int tx = tid & 31;        // col group: cols tx*4 .. +3
    int ty = tid >> 5;        // row group: rows ty*4 .. +3 (== warp id)
    int rb = blockIdx.x * GBM;

    // ---- load X tile (32 rows x 128 k) transposed into Xs ----
    // coalesced global float4 reads; warp-constant row -> padded STS 4-way
#pragma unroll
    for (int u = 0; u < 4; u++) {
        int id = tid + u * 256;       // 0..1023 float4 slots
        int r  = id >> 5;             // 0..31 (warp-constant)
        int kf = (id & 31) * 4;       // k offset of the float4
        float4 v = make_float4(0.f, 0.f, 0.f, 0.f);
        if (rb + r < M) v = *(const float4*)&X[(rb + r) * HID + kf];
        Xs[(kf + 0) * XS_STRIDE + r] = v.x;
        Xs[(kf + 1) * XS_STRIDE + r] = v.y;
        Xs[(kf + 2) * XS_STRIDE + r] = v.z;
        Xs[(kf + 3) * XS_STRIDE + r] = v.w;
    }

    // ---- prefetch W chunk 0 ----
    {
#pragma unroll
        for (int u = 0; u < 4; u++) {
            int id = tid + u * 256;
            int row = id >> 5;
            int cf = (id & 31) * 4;
            cp16(&Ws[row * HID + cf], &W[row * HID + cf]);
        }
        cp_commit();
    }

    float acc[4][4];
#pragma unroll
    for (int i = 0; i < 4; i++)
#pragma unroll
        for (int j = 0; j < 4; j++) acc[i][j] = 0.0f;

#pragma unroll
    for (int t = 0; t < 4; t++) {
        cp_wait0();
        __syncthreads();   // chunk t visible to everyone; iter t-1 compute done
        if (t < 3) {
            int kt = (t + 1) * 32;
            int buf = (t + 1) & 1;
#pragma unroll
            for (int u = 0; u < 4; u++) {
                int id = tid + u * 256;
                int row = id >> 5;
                int cf = (id & 31) * 4;
                cp16(&Ws[(buf * 32 + row) * HID + cf], &W[(kt + row) * HID + cf]);
            }
            cp_commit();
        }
        const float* Wb = &Ws[(t & 1) * 32 * HID];
        int kbase = t * 32;
#pragma unroll
        for (int kk = 0; kk < 32; kk++) {
            const float* xrow = &Xs[(kbase + kk) * XS_STRIDE + ty * 4];
            float a0 = xrow[0];
            float a1 = xrow[1];
            float a2 = xrow[2];
            float a3 = xrow[3];
            float4 b = *(const float4*)&Wb[kk * HID + tx * 4];
            acc[0][0] = fmaf(a0, b.x, acc[0][0]);
            acc[0][1] = fmaf(a0, b.y, acc[0][1]);
            acc[0][2] = fmaf(a0, b.z, acc[0][2]);
            acc[0][3] = fmaf(a0, b.w, acc[0][3]);
            acc[1][0] = fmaf(a1, b.x, acc[1][0]);
            acc[1][1] = fmaf(a1, b.y, acc[1][1]);
            acc[1][2] = fmaf(a1, b.z, acc[1][2]);
            acc[1][3] = fmaf(a1, b.w, acc[1][3]);
            acc[2][0] = fmaf(a2, b.x, acc[2][0]);
            acc[2][1] = fmaf(a2, b.y, acc[2][1]);
            acc[2][2] = fmaf(a2, b.z, acc[2][2]);
            acc[2][3] = fmaf(a2, b.w, acc[2][3]);
            acc[3][0] = fmaf(a3, b.x, acc[3][0]);
            acc[3][1] = fmaf(a3, b.y, acc[3][1]);
            acc[3][2] = fmaf(a3, b.z, acc[3][2]);
            acc[3][3] = fmaf(a3, b.w, acc[3][3]);
        }
    }

    // ---- epilogue: scale by dis[row], store ----
#pragma unroll
    for (int i = 0; i < 4; i++) {
        int gr = rb + ty * 4 + i;
        if (gr < M) {
            float d = g_dis[gr];
            float4 o;
            o.x = acc[i][0] * d;
            o.y = acc[i][1] * d;
            o.z = acc[i][2] * d;
            o.w = acc[i][3] * d;
            *(float4*)&H[gr * HID + tx * 4] = o;
        }
    }
}

// ---------------- aggregation: warp per node, CSR gather, unrolled ----------------
__global__ __launch_bounds__(256) void agg_kernel(const float* __restrict__ HS,
                                                  const float* __restrict__ bias,
                                                  float* __restrict__ OUT, int relu) {
    int warp = (blockIdx.x * blockDim.x + threadIdx.x) >> 5;
    int lane = threadIdx.x & 31;
    if (warp >= N_NODES) return;
    int e0 = g_rowptr[warp];
    int e1 = g_rowptr[warp + 1];
    float4 acc = *(const float4*)&HS[warp * HID + lane * 4];  // self-loop term

    int base = e0;
    for (; base + 32 <= e1; base += 32) {
        int s = g_col[base + lane];
#pragma unroll
        for (int jj = 0; jj < 4; jj++) {
            float4 v[8];
#pragma unroll
            for (int j2 = 0; j2 < 8; j2++) {
                int ss = __shfl_sync(0xffffffffu, s, jj * 8 + j2);
                v[j2] = *(const float4*)&HS[ss * HID + lane * 4];
            }
#pragma unroll
            for (int j2 = 0; j2 < 8; j2++) {
                acc.x += v[j2].x; acc.y += v[j2].y;
                acc.z += v[j2].z; acc.w += v[j2].w;
            }
        }
    }
    int rem = e1 - base;
    if (rem > 0) {
        int s = (lane < rem) ? g_col[base + lane] : 0;
        for (int j = 0; j < rem; j++) {
            int ss = __shfl_sync(0xffffffffu, s, j);
            float4 v = *(const float4*)&HS[ss * HID + lane * 4];
            acc.x += v.x; acc.y += v.y; acc.z += v.z; acc.w += v.w;
        }
    }

    float d = g_dis[warp];
    float4 bb = *(const float4*)&bias[lane * 4];
    float4 o;
    o.x = acc.x * d + bb.x;
    o.y = acc.y * d + bb.y;
    o.z = acc.z * d + bb.z;
    o.w = acc.w * d + bb.w;
    if (relu) {
        o.x = fmaxf(o.x, 0.f); o.y = fmaxf(o.y, 0.f);
        o.z = fmaxf(o.z, 0.f); o.w = fmaxf(o.w, 0.f);
    }
    *(float4*)&OUT[warp * HID + lane * 4] = o;
}

// ---------------- mean pool: batch is sorted -> segment sums, no atomics ----------
__device__ __forceinline__ int lower_bound_dev(const int* __restrict__ a, int n, int key) {
    int lo = 0, hi = n;
    while (lo < hi) {
        int mid = (lo + hi) >> 1;
        if (a[mid] < key) lo = mid + 1; else hi = mid;
    }
    return lo;
}

__global__ __launch_bounds__(256) void pool_kernel(const float* __restrict__ H,
                                                   const int* __restrict__ batch,
                                                   float* __restrict__ out) {
    int g = blockIdx.x;
    int t = threadIdx.x;          // 256 threads: 2 row-halves x 128 cols
    int lo = lower_bound_dev(batch, N_NODES, g);
    int hi = lower_bound_dev(batch, N_NODES, g + 1);
    int c = t & 127;
    int half = t >> 7;
    float sum = 0.0f;
    int r = lo + half;
    for (; r + 6 < hi; r += 8) {
        float v0 = H[(r + 0) * HID + c];
        float v1 = H[(r + 2) * HID + c];
        float v2 = H[(r + 4) * HID + c];
        float v3 = H[(r + 6) * HID + c];
        sum += v0 + v1 + v2 + v3;
    }
    for (; r < hi; r += 2) sum += H[r * HID + c];
    __shared__ float red[256];
    red[t] = sum;
    __syncthreads();
    if (t < 128) {
        float tot = red[t] + red[t + 128];
        int n = hi - lo;
        out[g * HID + t] = tot / (float)max(n, 1);
    }
}

// ---------------- launch ----------------
extern "C" void kernel_launch(void* const* d_in, const int* in_sizes, int n_in,
                              void* d_out, int out_size) {
    const float* x     = (const float*)d_in[0];
    const int*   eidx  = (const int*)d_in[1];
    const int*   batch = (const int*)d_in[2];
    const float* W0    = (const float*)d_in[3];
    const float* b0    = (const float*)d_in[4];
    const float* W1    = (const float*)d_in[5];
    const float* b1    = (const float*)d_in[6];
    const float* W2    = (const float*)d_in[7];
    const float* b2    = (const float*)d_in[8];
    float* out = (float*)d_out;

    const int* src = eidx;
    const int* dst = eidx + N_EDGES;

    float* hs = nullptr;
    float* xb = nullptr;
    int* degp = nullptr;
    cudaGetSymbolAddress((void**)&hs, g_hs);
    cudaGetSymbolAddress((void**)&xb, g_xb);
    cudaGetSymbolAddress((void**)&degp, g_deg);

    static bool attr_set = false;
    if (!attr_set) {
        cudaFuncSetAttribute(gemm_kernel,
                             cudaFuncAttributeMaxDynamicSharedMemorySize,
                             GEMM_SMEM_BYTES);
        attr_set = true;
    }

    cudaMemsetAsync(degp, 0, N_NODES * sizeof(int));

    int e4_grid = (N_EDGES / 4 + 255) / 256;
    pos_kernel<<<e4_grid, 256>>>(dst);
    scan_kernel<<<1, 1024>>>();
    fill_kernel<<<e4_grid, 256>>>(src, dst);

    int gemm_grid = (N_NODES + GBM - 1) / GBM;   // 313
    int agg_grid = (N_NODES + 7) / 8;            // 8 warps per 256-thread block

    // layer 0
    gemm_kernel<<<gemm_grid, 256, GEMM_SMEM_BYTES>>>(x, W0, hs, N_NODES);
    agg_kernel<<<agg_grid, 256>>>(hs, b0, xb, 1);
    // layer 1
    gemm_kernel<<<gemm_grid, 256, GEMM_SMEM_BYTES>>>(xb, W1, hs, N_NODES);
    agg_kernel<<<agg_grid, 256>>>(hs, b1, xb, 1);
    // layer 2
    gemm_kernel<<<gemm_grid, 256, GEMM_SMEM_BYTES>>>(xb, W2, hs, N_NODES);
    agg_kernel<<<agg_grid, 256>>>(hs, b2, xb, 0);

    pool_kernel<<<N_GRAPHS, 256>>>(xb, batch, out);
}

// round 4
// speedup vs baseline: 1.5574x; 1.1342x over previous
#include <cuda_runtime.h>
#include <cuda_bf16.h>
#include <cstdint>

#define N_NODES 10000
#define N_EDGES 640000
#define HID 128
#define N_GRAPHS 64

// ---------------- device scratch (no dynamic alloc allowed) ----------------
__device__ int   g_deg[N_NODES];
__device__ float g_dis[N_NODES];
__device__ int   g_rowptr[N_NODES + 1];
__device__ int   g_pos[N_EDGES];          // slot of edge within its dst row
__device__ int   g_col[N_EDGES];          // src ids grouped by dst (CSR)
__device__ float g_hs[N_NODES * HID];     // (X @ W) * dis[row]
__device__ float g_xb[N_NODES * HID];     // layer output / next layer input

// ---------------- degree histogram over dst; record slot per edge ----------
__global__ __launch_bounds__(256) void pos_kernel(const int* __restrict__ dst) {
    int base = (blockIdx.x * blockDim.x + threadIdx.x) * 4;
    if (base + 3 < N_EDGES) {
        int d0 = dst[base + 0];
        int d1 = dst[base + 1];
        int d2 = dst[base + 2];
        int d3 = dst[base + 3];
        g_pos[base + 0] = atomicAdd(&g_deg[d0], 1);
        g_pos[base + 1] = atomicAdd(&g_deg[d1], 1);
        g_pos[base + 2] = atomicAdd(&g_deg[d2], 1);
        g_pos[base + 3] = atomicAdd(&g_deg[d3], 1);
    } else {
        for (int e = base; e < N_EDGES; e++)
            g_pos[e] = atomicAdd(&g_deg[dst[e]], 1);
    }
}

// ---------------- single-block scan: rowptr, dis ----------------
__global__ void scan_kernel() {
    __shared__ int ps[1024];
    const int C = 10;  // 1024 * 10 >= N_NODES
    int tid = threadIdx.x;
    int start = tid * C;
    int sum = 0;
#pragma unroll
    for (int i = 0; i < C; i++) {
        int idx = start + i;
        if (idx < N_NODES) sum += g_deg[idx];
    }
    ps[tid] = sum;
    __syncthreads();
    for (int off = 1; off < 1024; off <<= 1) {
        int v = (tid >= off) ? ps[tid - off] : 0;
        __syncthreads();
        ps[tid] += v;
        __syncthreads();
    }
    int run = (tid == 0) ? 0 : ps[tid - 1];
#pragma unroll
    for (int i = 0; i < C; i++) {
        int idx = start + i;
        if (idx < N_NODES) {
            int d = g_deg[idx];
            g_rowptr[idx] = run;
            g_dis[idx] = rsqrtf((float)(d + 1));
            run += d;
        }
    }
    if (tid == 1023) g_rowptr[N_NODES] = ps[1023];
}

// ---------------- CSR fill: pure scatter, no atomics ----------------
__global__ __launch_bounds__(256) void fill_kernel(const int* __restrict__ src,
                                                   const int* __restrict__ dst) {
    int base = (blockIdx.x * blockDim.x + threadIdx.x) * 4;
    if (base + 3 < N_EDGES) {
        int d0 = dst[base + 0], d1 = dst[base + 1];
        int d2 = dst[base + 2], d3 = dst[base + 3];
        int p0 = g_rowptr[d0] + g_pos[base + 0];
        int p1 = g_rowptr[d1] + g_pos[base + 1];
        int p2 = g_rowptr[d2] + g_pos[base + 2];
        int p3 = g_rowptr[d3] + g_pos[base + 3];
        g_col[p0] = src[base + 0];
        g_col[p1] = src[base + 1];
        g_col[p2] = src[base + 2];
        g_col[p3] = src[base + 3];
    } else {
        for (int e = base; e < N_EDGES; e++)
            g_col[g_rowptr[dst[e]] + g_pos[e]] = src[e];
    }
}

// ---------------- tf32 tensor-core GEMM ----------------
// H[r][c] = (sum_k X[r][k] * W[k][c]) * dis[r]
// BM=64 rows/block, full N=128, full K=128 in smem (tf32), 256 threads.
// mma.sync.m16n8k8 tf32; warps: 4 in M (16 rows each) x 2 in N (64 cols each).
// Smem stride 136 floats => bank = (8*gid + tig) % 32, conflict-free for both
// A and B fragment load patterns.
#define TBM 64
#define SMS 136
#define GEMM_SMEM_BYTES ((64 * SMS + 128 * SMS) * 4)

__device__ __forceinline__ uint32_t f2tf(float f) {
    uint32_t u;
    asm("cvt.rna.tf32.f32 %0, %1;" : "=r"(u) : "f"(f));
    return u;
}

__global__ __launch_bounds__(256) void gemm_kernel(const float* __restrict__ X,
                                                   const float* __restrict__ W,
                                                   float* __restrict__ H, int M) {
    extern __shared__ uint32_t smu[];
    uint32_t* Xs = smu;              // [64][136] tf32
    uint32_t* Ws = smu + 64 * SMS;   // [128][136] tf32
    int tid = threadIdx.x;
    int lane = tid & 31;
    int wid = tid >> 5;
    int rb = blockIdx.x * TBM;

    // ---- stage X (64x128) -> tf32 smem ----
#pragma unroll
    for (int u = 0; u < 8; u++) {
        int id = tid + u * 256;      // 2048 float4 slots
        int r = id >> 5;
        int c4 = (id & 31) * 4;
        float4 v = make_float4(0.f, 0.f, 0.f, 0.f);
        if (rb + r < M) v = *(const float4*)&X[(rb + r) * HID + c4];
        uint32_t* d = &Xs[r * SMS + c4];
        d[0] = f2tf(v.x); d[1] = f2tf(v.y); d[2] = f2tf(v.z); d[3] = f2tf(v.w);
    }
    // ---- stage W (128x128) -> tf32 smem ----
#pragma unroll
    for (int u = 0; u < 16; u++) {
        int id = tid + u * 256;      // 4096 float4 slots
        int r = id >> 5;
        int c4 = (id & 31) * 4;
        float4 v = *(const float4*)&W[r * HID + c4];
        uint32_t* d = &Ws[r * SMS + c4];
        d[0] = f2tf(v.x); d[1] = f2tf(v.y); d[2] = f2tf(v.z); d[3] = f2tf(v.w);
    }
    __syncthreads();

    int gid = lane >> 2;     // 0..7
    int tig = lane & 3;      // 0..3
    int wm = wid & 3;        // M-slab (16 rows)
    int wn = wid >> 2;       // N-half (64 cols)
    int arow = wm * 16 + gid;
    int ncol = wn * 64;

    float d0[8], d1[8], d2[8], d3[8];
#pragma unroll
    for (int t = 0; t < 8; t++) { d0[t] = d1[t] = d2[t] = d3[t] = 0.f; }

#pragma unroll 4
    for (int k0 = 0; k0 < 128; k0 += 8) {
        uint32_t a0 = Xs[arow * SMS + k0 + tig];
        uint32_t a1 = Xs[(arow + 8) * SMS + k0 + tig];
        uint32_t a2 = Xs[arow * SMS + k0 + tig + 4];
        uint32_t a3 = Xs[(arow + 8) * SMS + k0 + tig + 4];
        const uint32_t* wr0 = &Ws[(k0 + tig) * SMS + ncol + gid];
        const uint32_t* wr1 = &Ws[(k0 + tig + 4) * SMS + ncol + gid];
        uint32_t b0[8], b1[8];
#pragma unroll
        for (int t = 0; t < 8; t++) {
            b0[t] = wr0[t * 8];
            b1[t] = wr1[t * 8];
        }
#pragma unroll
        for (int t = 0; t < 8; t++) {
            asm volatile(
                "mma.sync.aligned.m16n8k8.row.col.f32.tf32.tf32.f32 "
                "{%0,%1,%2,%3}, {%4,%5,%6,%7}, {%8,%9}, {%0,%1,%2,%3};\n"
                : "+f"(d0[t]), "+f"(d1[t]), "+f"(d2[t]), "+f"(d3[t])
                : "r"(a0), "r"(a1), "r"(a2), "r"(a3), "r"(b0[t]), "r"(b1[t]));
        }
    }

    // ---- epilogue: scale by dis[row], store ----
    int r0 = rb + arow;
    int r1 = r0 + 8;
    float dis0 = (r0 < M) ? g_dis[r0] : 0.f;
    float dis1 = (r1 < M) ? g_dis[r1] : 0.f;
#pragma unroll
    for (int t = 0; t < 8; t++) {
        int c = ncol + t * 8 + tig * 2;
        if (r0 < M) {
            float2 o; o.x = d0[t] * dis0; o.y = d1[t] * dis0;
            *(float2*)&H[r0 * HID + c] = o;
        }
        if (r1 < M) {
            float2 o; o.x = d2[t] * dis1; o.y = d3[t] * dis1;
            *(float2*)&H[r1 * HID + c] = o;
        }
    }
}

// ---------------- aggregation: warp per node, CSR gather, unrolled ----------------
__global__ __launch_bounds__(256) void agg_kernel(const float* __restrict__ HS,
                                                  const float* __restrict__ bias,
                                                  float* __restrict__ OUT, int relu) {
    int warp = (blockIdx.x * blockDim.x + threadIdx.x) >> 5;
    int lane = threadIdx.x & 31;
    if (warp >= N_NODES) return;
    int e0 = g_rowptr[warp];
    int e1 = g_rowptr[warp + 1];
    float4 acc = *(const float4*)&HS[warp * HID + lane * 4];  // self-loop term

    int base = e0;
    for (; base + 32 <= e1; base += 32) {
        int s = g_col[base + lane];
#pragma unroll
        for (int jj = 0; jj < 4; jj++) {
            float4 v[8];
#pragma unroll
            for (int j2 = 0; j2 < 8; j2++) {
                int ss = __shfl_sync(0xffffffffu, s, jj * 8 + j2);
                v[j2] = *(const float4*)&HS[ss * HID + lane * 4];
            }
#pragma unroll
            for (int j2 = 0; j2 < 8; j2++) {
                acc.x += v[j2].x; acc.y += v[j2].y;
                acc.z += v[j2].z; acc.w += v[j2].w;
            }
        }
    }
    int rem = e1 - base;
    if (rem > 0) {
        int s = (lane < rem) ? g_col[base + lane] : 0;
        for (int j = 0; j < rem; j++) {
            int ss = __shfl_sync(0xffffffffu, s, j);
            float4 v = *(const float4*)&HS[ss * HID + lane * 4];
            acc.x += v.x; acc.y += v.y; acc.z += v.z; acc.w += v.w;
        }
    }

    float d = g_dis[warp];
    float4 bb = *(const float4*)&bias[lane * 4];
    float4 o;
    o.x = acc.x * d + bb.x;
    o.y = acc.y * d + bb.y;
    o.z = acc.z * d + bb.z;
    o.w = acc.w * d + bb.w;
    if (relu) {
        o.x = fmaxf(o.x, 0.f); o.y = fmaxf(o.y, 0.f);
        o.z = fmaxf(o.z, 0.f); o.w = fmaxf(o.w, 0.f);
    }
    *(float4*)&OUT[warp * HID + lane * 4] = o;
}

// ---------------- mean pool: batch is sorted -> segment sums, no atomics ----------
__device__ __forceinline__ int lower_bound_dev(const int* __restrict__ a, int n, int key) {
    int lo = 0, hi = n;
    while (lo < hi) {
        int mid = (lo + hi) >> 1;
        if (a[mid] < key) lo = mid + 1; else hi = mid;
    }
    return lo;
}

__global__ __launch_bounds__(256) void pool_kernel(const float* __restrict__ H,
                                                   const int* __restrict__ batch,
                                                   float* __restrict__ out) {
    int g = blockIdx.x;
    int t = threadIdx.x;          // 256 threads: 2 row-halves x 128 cols
    int lo = lower_bound_dev(batch, N_NODES, g);
    int hi = lower_bound_dev(batch, N_NODES, g + 1);
    int c = t & 127;
    int half = t >> 7;
    float sum = 0.0f;
    int r = lo + half;
    for (; r + 6 < hi; r += 8) {
        float v0 = H[(r + 0) * HID + c];
        float v1 = H[(r + 2) * HID + c];
        float v2 = H[(r + 4) * HID + c];
        float v3 = H[(r + 6) * HID + c];
        sum += v0 + v1 + v2 + v3;
    }
    for (; r < hi; r += 2) sum += H[r * HID + c];
    __shared__ float red[256];
    red[t] = sum;
    __syncthreads();
    if (t < 128) {
        float tot = red[t] + red[t + 128];
        int n = hi - lo;
        out[g * HID + t] = tot / (float)max(n, 1);
    }
}

// ---------------- launch ----------------
extern "C" void kernel_launch(void* const* d_in, const int* in_sizes, int n_in,
                              void* d_out, int out_size) {
    const float* x     = (const float*)d_in[0];
    const int*   eidx  = (const int*)d_in[1];
    const int*   batch = (const int*)d_in[2];
    const float* W0    = (const float*)d_in[3];
    const float* b0    = (const float*)d_in[4];
    const float* W1    = (const float*)d_in[5];
    const float* b1    = (const float*)d_in[6];
    const float* W2    = (const float*)d_in[7];
    const float* b2    = (const float*)d_in[8];
    float* out = (float*)d_out;

    const int* src = eidx;
    const int* dst = eidx + N_EDGES;

    float* hs = nullptr;
    float* xb = nullptr;
    int* degp = nullptr;
    cudaGetSymbolAddress((void**)&hs, g_hs);
    cudaGetSymbolAddress((void**)&xb, g_xb);
    cudaGetSymbolAddress((void**)&degp, g_deg);

    static bool attr_set = false;
    if (!attr_set) {
        cudaFuncSetAttribute(gemm_kernel,
                             cudaFuncAttributeMaxDynamicSharedMemorySize,
                             GEMM_SMEM_BYTES);
        attr_set = true;
    }

    cudaMemsetAsync(degp, 0, N_NODES * sizeof(int));

    int e4_grid = (N_EDGES / 4 + 255) / 256;
    pos_kernel<<<e4_grid, 256>>>(dst);
    scan_kernel<<<1, 1024>>>();
    fill_kernel<<<e4_grid, 256>>>(src, dst);

    int gemm_grid = (N_NODES + TBM - 1) / TBM;   // 157
    int agg_grid = (N_NODES + 7) / 8;            // 8 warps per 256-thread block

    // layer 0
    gemm_kernel<<<gemm_grid, 256, GEMM_SMEM_BYTES>>>(x, W0, hs, N_NODES);
    agg_kernel<<<agg_grid, 256>>>(hs, b0, xb, 1);
    // layer 1
    gemm_kernel<<<gemm_grid, 256, GEMM_SMEM_BYTES>>>(xb, W1, hs, N_NODES);
    agg_kernel<<<agg_grid, 256>>>(hs, b1, xb, 1);
    // layer 2
    gemm_kernel<<<gemm_grid, 256, GEMM_SMEM_BYTES>>>(xb, W2, hs, N_NODES);
    agg_kernel<<<agg_grid, 256>>>(hs, b2, xb, 0);

    pool_kernel<<<N_GRAPHS, 256>>>(xb, batch, out);
}

// round 5
// speedup vs baseline: 1.9368x; 1.2436x over previous
#include <cuda_runtime.h>
#include <cuda_fp16.h>
#include <cstdint>

#define N_NODES 10000
#define N_EDGES 640000
#define HID 128
#define N_GRAPHS 64

// ---------------- device scratch (no dynamic alloc allowed) ----------------
__device__ int    g_deg[N_NODES];
__device__ float  g_dis[N_NODES];
__device__ int    g_rowptr[N_NODES + 1];
__device__ int    g_pos[N_EDGES];          // slot of edge within its dst row
__device__ int    g_col[N_EDGES];          // src ids grouped by dst (CSR)
__device__ __half g_hs[N_NODES * HID];     // fp16: (X @ W) * dis[row]
__device__ float  g_xb[N_NODES * HID];     // layer output / next layer input (fp32)

// ---------------- degree histogram over dst; record slot per edge ----------
__global__ __launch_bounds__(256) void pos_kernel(const int* __restrict__ dst) {
    int base = (blockIdx.x * blockDim.x + threadIdx.x) * 4;
    if (base + 3 < N_EDGES) {
        int d0 = dst[base + 0];
        int d1 = dst[base + 1];
        int d2 = dst[base + 2];
        int d3 = dst[base + 3];
        g_pos[base + 0] = atomicAdd(&g_deg[d0], 1);
        g_pos[base + 1] = atomicAdd(&g_deg[d1], 1);
        g_pos[base + 2] = atomicAdd(&g_deg[d2], 1);
        g_pos[base + 3] = atomicAdd(&g_deg[d3], 1);
    } else {
        for (int e = base; e < N_EDGES; e++)
            g_pos[e] = atomicAdd(&g_deg[dst[e]], 1);
    }
}

// ---------------- single-block scan: rowptr, dis ----------------
__global__ void scan_kernel() {
    __shared__ int ps[1024];
    const int C = 10;  // 1024 * 10 >= N_NODES
    int tid = threadIdx.x;
    int start = tid * C;
    int sum = 0;
#pragma unroll
    for (int i = 0; i < C; i++) {
        int idx = start + i;
        if (idx < N_NODES) sum += g_deg[idx];
    }
    ps[tid] = sum;
    __syncthreads();
    for (int off = 1; off < 1024; off <<= 1) {
        int v = (tid >= off) ? ps[tid - off] : 0;
        __syncthreads();
        ps[tid] += v;
        __syncthreads();
    }
    int run = (tid == 0) ? 0 : ps[tid - 1];
#pragma unroll
    for (int i = 0; i < C; i++) {
        int idx = start + i;
        if (idx < N_NODES) {
            int d = g_deg[idx];
            g_rowptr[idx] = run;
            g_dis[idx] = rsqrtf((float)(d + 1));
            run += d;
        }
    }
    if (tid == 1023) g_rowptr[N_NODES] = ps[1023];
}

// ---------------- CSR fill: pure scatter, no atomics ----------------
__global__ __launch_bounds__(256) void fill_kernel(const int* __restrict__ src,
                                                   const int* __restrict__ dst) {
    int base = (blockIdx.x * blockDim.x + threadIdx.x) * 4;
    if (base + 3 < N_EDGES) {
        int d0 = dst[base + 0], d1 = dst[base + 1];
        int d2 = dst[base + 2], d3 = dst[base + 3];
        int p0 = g_rowptr[d0] + g_pos[base + 0];
        int p1 = g_rowptr[d1] + g_pos[base + 1];
        int p2 = g_rowptr[d2] + g_pos[base + 2];
        int p3 = g_rowptr[d3] + g_pos[base + 3];
        g_col[p0] = src[base + 0];
        g_col[p1] = src[base + 1];
        g_col[p2] = src[base + 2];
        g_col[p3] = src[base + 3];
    } else {
        for (int e = base; e < N_EDGES; e++)
            g_col[g_rowptr[dst[e]] + g_pos[e]] = src[e];
    }
}

// ---------------- fp16 tensor-core GEMM ----------------
// H[r][c] = half( (sum_k X[r][k]*W[k][c]) * dis[r] )
// 64 rows/block, full N=128, full K=128 in smem as fp16, 256 threads.
// mma.m16n8k16.f16 (fp32 accum). A via ldmatrix.x4, B via ldmatrix.x4.trans.
// Half-stride 136 (272 B rows): ldmatrix rows land on distinct 4-bank groups.
#define TBM 64
#define SMH 136
#define GEMM_SMEM_BYTES ((64 + 128) * SMH * 2)

__global__ __launch_bounds__(256) void gemm_kernel(const float* __restrict__ X,
                                                   const float* __restrict__ W,
                                                   __half* __restrict__ H, int M) {
    extern __shared__ __half smh[];
    __half* Xs = smh;             // [64][SMH]
    __half* Ws = smh + 64 * SMH;  // [128][SMH], layout [k][n]
    int tid = threadIdx.x;
    int lane = tid & 31;
    int wid = tid >> 5;
    int rb = blockIdx.x * TBM;

    // ---- stage X (64x128 fp32 -> fp16) ----
#pragma unroll
    for (int u = 0; u < 8; u++) {
        int id = tid + u * 256;       // 2048 float4 slots
        int r = id >> 5;
        int c4 = (id & 31) * 4;
        float4 v = make_float4(0.f, 0.f, 0.f, 0.f);
        if (rb + r < M) v = *(const float4*)&X[(rb + r) * HID + c4];
        *(__half2*)&Xs[r * SMH + c4 + 0] = __floats2half2_rn(v.x, v.y);
        *(__half2*)&Xs[r * SMH + c4 + 2] = __floats2half2_rn(v.z, v.w);
    }
    // ---- stage W (128x128 fp32 -> fp16), natural [k][n] ----
#pragma unroll
    for (int u = 0; u < 16; u++) {
        int id = tid + u * 256;       // 4096 float4 slots
        int r = id >> 5;
        int c4 = (id & 31) * 4;
        float4 v = *(const float4*)&W[r * HID + c4];
        *(__half2*)&Ws[r * SMH + c4 + 0] = __floats2half2_rn(v.x, v.y);
        *(__half2*)&Ws[r * SMH + c4 + 2] = __floats2half2_rn(v.z, v.w);
    }
    __syncthreads();

    int gid = lane >> 2;     // 0..7
    int tig = lane & 3;      // 0..3
    int wm = wid & 3;        // M-slab (16 rows)
    int wn = wid >> 2;       // N-half (64 cols)
    int tr = lane & 7;       // ldmatrix row-in-tile
    int tt = lane >> 3;      // ldmatrix tile id

    // A tiles: t0=(rows 0-7,k0-7) t1=(rows 8-15,k0-7) t2=(rows 0-7,k8-15) t3=(rows 8-15,k8-15)
    uint32_t xs_base = (uint32_t)__cvta_generic_to_shared(Xs);
    uint32_t ws_base = (uint32_t)__cvta_generic_to_shared(Ws);
    uint32_t a_addr0 = xs_base +
        (((wm * 16 + (tt & 1) * 8 + tr) * SMH + (tt >> 1) * 8) << 1);
    // B tiles (per p): t0=(k0-7,n0-7) t1=(k8-15,n0-7) t2=(k0-7,n8-15) t3=(k8-15,n8-15)
    uint32_t b_addr0 = ws_base +
        ((((tt & 1) * 8 + tr) * SMH + wn * 64 + (tt >> 1) * 8) << 1);

    float d0[8], d1[8], d2[8], d3[8];
#pragma unroll
    for (int t = 0; t < 8; t++) { d0[t] = d1[t] = d2[t] = d3[t] = 0.f; }

#pragma unroll
    for (int k0 = 0; k0 < 128; k0 += 16) {
        uint32_t a0, a1, a2, a3;
        asm volatile("ldmatrix.sync.aligned.m8n8.x4.shared.b16 {%0,%1,%2,%3}, [%4];"
                     : "=r"(a0), "=r"(a1), "=r"(a2), "=r"(a3)
                     : "r"(a_addr0 + (k0 << 1)));
#pragma unroll
        for (int p = 0; p < 4; p++) {
            uint32_t b0a, b1a, b0b, b1b;
            asm volatile("ldmatrix.sync.aligned.m8n8.x4.trans.shared.b16 {%0,%1,%2,%3}, [%4];"
                         : "=r"(b0a), "=r"(b1a), "=r"(b0b), "=r"(b1b)
                         : "r"(b_addr0 + ((k0 * SMH + p * 16) << 1)));
            int t0 = 2 * p;
            int t1 = 2 * p + 1;
            asm volatile(
                "mma.sync.aligned.m16n8k16.row.col.f32.f16.f16.f32 "
                "{%0,%1,%2,%3}, {%4,%5,%6,%7}, {%8,%9}, {%0,%1,%2,%3};\n"
                : "+f"(d0[t0]), "+f"(d1[t0]), "+f"(d2[t0]), "+f"(d3[t0])
                : "r"(a0), "r"(a1), "r"(a2), "r"(a3), "r"(b0a), "r"(b1a));
            asm volatile(
                "mma.sync.aligned.m16n8k16.row.col.f32.f16.f16.f32 "
                "{%0,%1,%2,%3}, {%4,%5,%6,%7}, {%8,%9}, {%0,%1,%2,%3};\n"
                : "+f"(d0[t1]), "+f"(d1[t1]), "+f"(d2[t1]), "+f"(d3[t1])
                : "r"(a0), "r"(a1), "r"(a2), "r"(a3), "r"(b0b), "r"(b1b));
        }
    }

    // ---- epilogue: scale by dis[row], convert to fp16, store ----
    // c frag: d0,d1 = row gid cols 2tig,2tig+1 ; d2,d3 = row gid+8 same cols
    int arow = wm * 16 + gid;
    int ncol = wn * 64;
    int r0 = rb + arow;
    int r1 = r0 + 8;
    float dis0 = (r0 < M) ? g_dis[r0] : 0.f;
    float dis1 = (r1 < M) ? g_dis[r1] : 0.f;
#pragma unroll
    for (int t = 0; t < 8; t++) {
        int c = ncol + t * 8 + tig * 2;
        if (r0 < M)
            *(__half2*)&H[r0 * HID + c] = __floats2half2_rn(d0[t] * dis0, d1[t] * dis0);
        if (r1 < M)
            *(__half2*)&H[r1 * HID + c] = __floats2half2_rn(d2[t] * dis1, d3[t] * dis1);
    }
}

// ---------------- aggregation: warp per node, fp16 CSR gather ----------------
// out[i] = dis[i] * (hs[i] + sum_{e: dst=i} hs[src_e]) + b ; optional relu
__global__ __launch_bounds__(256) void agg_kernel(const __half* __restrict__ HS_,
                                                  const float* __restrict__ bias,
                                                  float* __restrict__ OUT, int relu) {
    const uint2* HS = (const uint2*)HS_;   // 32 uint2 (8B) per 128-half row
    int warp = (blockIdx.x * blockDim.x + threadIdx.x) >> 5;
    int lane = threadIdx.x & 31;
    if (warp >= N_NODES) return;
    int e0 = g_rowptr[warp];
    int e1 = g_rowptr[warp + 1];

    float4 acc;
    {   // self-loop term
        uint2 sv = HS[warp * 32 + lane];
        float2 f0 = __half22float2(*(__half2*)&sv.x);
        float2 f1 = __half22float2(*(__half2*)&sv.y);
        acc.x = f0.x; acc.y = f0.y; acc.z = f1.x; acc.w = f1.y;
    }

    int base = e0;
    for (; base + 32 <= e1; base += 32) {
        int s = g_col[base + lane];
#pragma unroll
        for (int jj = 0; jj < 4; jj++) {
            uint2 v[8];
#pragma unroll
            for (int j2 = 0; j2 < 8; j2++) {
                int ss = __shfl_sync(0xffffffffu, s, jj * 8 + j2);
                v[j2] = HS[ss * 32 + lane];
            }
#pragma unroll
            for (int j2 = 0; j2 < 8; j2++) {
                float2 f0 = __half22float2(*(__half2*)&v[j2].x);
                float2 f1 = __half22float2(*(__half2*)&v[j2].y);
                acc.x += f0.x; acc.y += f0.y; acc.z += f1.x; acc.w += f1.y;
            }
        }
    }
    int rem = e1 - base;
    if (rem > 0) {
        int s = (lane < rem) ? g_col[base + lane] : 0;
        for (int j = 0; j < rem; j++) {
            int ss = __shfl_sync(0xffffffffu, s, j);
            uint2 v = HS[ss * 32 + lane];
            float2 f0 = __half22float2(*(__half2*)&v.x);
            float2 f1 = __half22float2(*(__half2*)&v.y);
            acc.x += f0.x; acc.y += f0.y; acc.z += f1.x; acc.w += f1.y;
        }
    }

    float d = g_dis[warp];
    float4 bb = *(const float4*)&bias[lane * 4];
    float4 o;
    o.x = acc.x * d + bb.x;
    o.y = acc.y * d + bb.y;
    o.z = acc.z * d + bb.z;
    o.w = acc.w * d + bb.w;
    if (relu) {
        o.x = fmaxf(o.x, 0.f); o.y = fmaxf(o.y, 0.f);
        o.z = fmaxf(o.z, 0.f); o.w = fmaxf(o.w, 0.f);
    }
    *(float4*)&OUT[warp * HID + lane * 4] = o;
}

// ---------------- mean pool: batch is sorted -> segment sums, no atomics ----------
__device__ __forceinline__ int lower_bound_dev(const int* __restrict__ a, int n, int key) {
    int lo = 0, hi = n;
    while (lo < hi) {
        int mid = (lo + hi) >> 1;
        if (a[mid] < key) lo = mid + 1; else hi = mid;
    }
    return lo;
}

__global__ __launch_bounds__(256) void pool_kernel(const float* __restrict__ H,
                                                   const int* __restrict__ batch,
                                                   float* __restrict__ out) {
    int g = blockIdx.x;
    int t = threadIdx.x;          // 256 threads: 2 row-halves x 128 cols
    int lo = lower_bound_dev(batch, N_NODES, g);
    int hi = lower_bound_dev(batch, N_NODES, g + 1);
    int c = t & 127;
    int half = t >> 7;
    float sum = 0.0f;
    int r = lo + half;
    for (; r + 6 < hi; r += 8) {
        float v0 = H[(r + 0) * HID + c];
        float v1 = H[(r + 2) * HID + c];
        float v2 = H[(r + 4) * HID + c];
        float v3 = H[(r + 6) * HID + c];
        sum += v0 + v1 + v2 + v3;
    }
    for (; r < hi; r += 2) sum += H[r * HID + c];
    __shared__ float red[256];
    red[t] = sum;
    __syncthreads();
    if (t < 128) {
        float tot = red[t] + red[t + 128];
        int n = hi - lo;
        out[g * HID + t] = tot / (float)max(n, 1);
    }
}

// ---------------- launch ----------------
extern "C" void kernel_launch(void* const* d_in, const int* in_sizes, int n_in,
                              void* d_out, int out_size) {
    const float* x     = (const float*)d_in[0];
    const int*   eidx  = (const int*)d_in[1];
    const int*   batch = (const int*)d_in[2];
    const float* W0    = (const float*)d_in[3];
    const float* b0    = (const float*)d_in[4];
    const float* W1    = (const float*)d_in[5];
    const float* b1    = (const float*)d_in[6];
    const float* W2    = (const float*)d_in[7];
    const float* b2    = (const float*)d_in[8];
    float* out = (float*)d_out;

    const int* src = eidx;
    const int* dst = eidx + N_EDGES;

    __half* hs = nullptr;
    float* xb = nullptr;
    int* degp = nullptr;
    cudaGetSymbolAddress((void**)&hs, g_hs);
    cudaGetSymbolAddress((void**)&xb, g_xb);
    cudaGetSymbolAddress((void**)&degp, g_deg);

    static bool attr_set = false;
    if (!attr_set) {
        cudaFuncSetAttribute(gemm_kernel,
                             cudaFuncAttributeMaxDynamicSharedMemorySize,
                             GEMM_SMEM_BYTES);
        attr_set = true;
    }

    cudaMemsetAsync(degp, 0, N_NODES * sizeof(int));

    int e4_grid = (N_EDGES / 4 + 255) / 256;
    pos_kernel<<<e4_grid, 256>>>(dst);
    scan_kernel<<<1, 1024>>>();
    fill_kernel<<<e4_grid, 256>>>(src, dst);

    int gemm_grid = (N_NODES + TBM - 1) / TBM;   // 157
    int agg_grid = (N_NODES + 7) / 8;            // 8 warps per 256-thread block

    // layer 0
    gemm_kernel<<<gemm_grid, 256, GEMM_SMEM_BYTES>>>(x, W0, hs, N_NODES);
    agg_kernel<<<agg_grid, 256>>>(hs, b0, xb, 1);
    // layer 1
    gemm_kernel<<<gemm_grid, 256, GEMM_SMEM_BYTES>>>(xb, W1, hs, N_NODES);
    agg_kernel<<<agg_grid, 256>>>(hs, b1, xb, 1);
    // layer 2
    gemm_kernel<<<gemm_grid, 256, GEMM_SMEM_BYTES>>>(xb, W2, hs, N_NODES);
    agg_kernel<<<agg_grid, 256>>>(hs, b2, xb, 0);

    pool_kernel<<<N_GRAPHS, 256>>>(xb, batch, out);
}